// round 7
// baseline (speedup 1.0000x reference)
#include <cuda_runtime.h>
#include <cuda_bf16.h>
#include <cstdint>
#include <cstddef>

// ---- problem constants ----
#define CH    256
#define CR    64
#define GRP   16
#define CPG   16
#define KK    49
#define HH    64
#define WW    64
#define NPIX  4096
#define BSZ   4

// ---- device scratch ----
__device__ float g_t[BSZ * CR * NPIX];        // 4 MB reduce output (L2-resident)

// ============================================================================
// warp-MMA helpers (baseline PTX, sm_80+ — compiles at .target sm_100)
// ============================================================================
__device__ __forceinline__ uint32_t smem_u32(const void* p) {
    uint32_t a;
    asm("{ .reg .u64 t; cvta.to.shared.u64 t, %1; cvt.u32.u64 %0, t; }"
        : "=r"(a) : "l"(p));
    return a;
}
__device__ __forceinline__ void ldmatrix_x4(uint32_t& a0, uint32_t& a1,
                                            uint32_t& a2, uint32_t& a3, uint32_t addr) {
    asm volatile("ldmatrix.sync.aligned.m8n8.x4.shared.b16 {%0,%1,%2,%3}, [%4];"
                 : "=r"(a0), "=r"(a1), "=r"(a2), "=r"(a3) : "r"(addr));
}
__device__ __forceinline__ void ldmatrix_x2_trans(uint32_t& b0, uint32_t& b1, uint32_t addr) {
    asm volatile("ldmatrix.sync.aligned.m8n8.x2.trans.shared.b16 {%0,%1}, [%2];"
                 : "=r"(b0), "=r"(b1) : "r"(addr));
}
__device__ __forceinline__ void mma_bf16(float* c, const uint32_t* a,
                                         uint32_t b0, uint32_t b1) {
    asm volatile("mma.sync.aligned.m16n8k16.row.col.f32.bf16.bf16.f32 "
                 "{%0,%1,%2,%3}, {%4,%5,%6,%7}, {%8,%9}, {%0,%1,%2,%3};"
                 : "+f"(c[0]), "+f"(c[1]), "+f"(c[2]), "+f"(c[3])
                 : "r"(a[0]), "r"(a[1]), "r"(a[2]), "r"(a[3]), "r"(b0), "r"(b1));
}

// ---- dynamic smem layout (float offsets) ----
// Phase A: T hi/lo (64 x pitch136 bf16), W hi/lo (64 x pitch72 bf16), ks out, bias
// Phase B: xs (9216 floats) aliases the T/W region.
#define T_PITCH  136        // bf16; 272B = 17 x 16B -> conflict-free ldmatrix
#define W_PITCH  72         // bf16; 144B = 9 x 16B
#define T_HI_F   0          // 64*136/2 = 4352 floats
#define T_LO_F   4352
#define W_HI_F   8704       // 64*72/2 = 2304 floats  (byte 34816, 16B-aligned)
#define W_LO_F   11008
#define KS_F     13312      // 49*128 = 6272 floats   (byte 53248)
#define BS_F     19584      // 56 floats
#define XS_F     0          // alias: 16*8*72 = 9216 floats (< 13312)
#define SMEM_FLOATS 19648
#define SMEM_BYTES  (SMEM_FLOATS * 4)

// ============================================================================
// Kernel 1: reduce (unchanged — measured ~16 us)
// ============================================================================
__global__ void __launch_bounds__(256) reduce_kernel(
        const float* __restrict__ x,
        const float* __restrict__ wr,
        const float* __restrict__ br) {
    __shared__ float4 ws4[32 * 64];
    const int b   = blockIdx.z;
    const int oc  = blockIdx.y;
    const int px0 = blockIdx.x * 64;
    const int tid = threadIdx.x;

    const float4* wsrc = reinterpret_cast<const float4*>(wr + (size_t)oc * 32 * CH);
    for (int i = tid; i < 2048; i += 256) ws4[i] = wsrc[i];
    __syncthreads();

    const int og = tid >> 5;
    const int pg = tid & 31;
    const int px = px0 + pg * 2;
    const float* xb = x + (size_t)b * CH * NPIX + px;

    float acc[4][2];
    #pragma unroll
    for (int i = 0; i < 4; ++i) { acc[i][0] = 0.f; acc[i][1] = 0.f; }

    #pragma unroll 4
    for (int k4 = 0; k4 < 64; ++k4) {
        const float2 x0 = *reinterpret_cast<const float2*>(xb + (size_t)(k4 * 4 + 0) * NPIX);
        const float2 x1 = *reinterpret_cast<const float2*>(xb + (size_t)(k4 * 4 + 1) * NPIX);
        const float2 x2 = *reinterpret_cast<const float2*>(xb + (size_t)(k4 * 4 + 2) * NPIX);
        const float2 x3 = *reinterpret_cast<const float2*>(xb + (size_t)(k4 * 4 + 3) * NPIX);
        #pragma unroll
        for (int oi = 0; oi < 4; ++oi) {
            const float4 wv = ws4[(og * 4 + oi) * 64 + k4];
            acc[oi][0] += wv.x * x0.x + wv.y * x1.x + wv.z * x2.x + wv.w * x3.x;
            acc[oi][1] += wv.x * x0.y + wv.y * x1.y + wv.z * x2.y + wv.w * x3.y;
        }
    }

    float* tb = g_t + (size_t)b * CR * NPIX + px;
    #pragma unroll
    for (int oi = 0; oi < 4; ++oi) {
        const int o = oc * 32 + og * 4 + oi;
        const float bias = br[o];
        float2 v; v.x = acc[oi][0] + bias; v.y = acc[oi][1] + bias;
        *reinterpret_cast<float2*>(tb + (size_t)o * NPIX) = v;
    }
}

// ============================================================================
// Kernel 2: fused span (mma.sync bf16 hi/lo 3-pass) + involution apply
// Block = (tile 0..31 [2 rows x 64 px], g, b) = 2048 blocks; 256 threads.
// Phase A: ks[49][128] = W_g[49][64] @ t[64][128] + bias  via m16n8k16 bf16 MMA.
//          warp = (mtile = w&3 [16 ks-rows], nhalf = w>>2 [64 px]); 96 MMA/warp.
// Phase B: scalar apply (validated in R4).
// ============================================================================
extern __shared__ float sm[];

__global__ void __launch_bounds__(256) fused_kernel(
        const float* __restrict__ x,
        const float* __restrict__ wspan,
        const float* __restrict__ bspan,
        float* __restrict__ out) {
    const int tile = blockIdx.x;
    const int g    = blockIdx.y;
    const int b    = blockIdx.z;
    const int tid  = threadIdx.x;
    const int p0g  = tile * 128;
    const int y0   = tile * 2;

    const uint32_t smb = smem_u32(sm);
    __nv_bfloat16* Thi = reinterpret_cast<__nv_bfloat16*>(sm + T_HI_F);
    __nv_bfloat16* Tlo = reinterpret_cast<__nv_bfloat16*>(sm + T_LO_F);
    __nv_bfloat16* Whi = reinterpret_cast<__nv_bfloat16*>(sm + W_HI_F);
    __nv_bfloat16* Wlo = reinterpret_cast<__nv_bfloat16*>(sm + W_LO_F);
    float* ksp = sm + KS_F;
    float* bss = sm + BS_F;
    float* xs  = sm + XS_F;

    // ---- stage t tile (64x128) and W slice (49x64, pad 64) as bf16 hi/lo ----
    {
        const float* tsrc = g_t + (size_t)b * CR * NPIX + p0g;
        for (int i = tid; i < 64 * 128; i += 256) {
            const int k = i >> 7, px = i & 127;
            const float v = tsrc[(size_t)k * NPIX + px];
            const __nv_bfloat16 h = __float2bfloat16(v);
            const __nv_bfloat16 l = __float2bfloat16(v - __bfloat162float(h));
            Thi[k * T_PITCH + px] = h;
            Tlo[k * T_PITCH + px] = l;
        }
        const float* wsl = wspan + (size_t)g * KK * 64;
        for (int i = tid; i < 64 * 64; i += 256) {
            const int m = i >> 6, k = i & 63;
            const float v = (m < KK) ? wsl[(size_t)m * 64 + k] : 0.f;
            const __nv_bfloat16 h = __float2bfloat16(v);
            const __nv_bfloat16 l = __float2bfloat16(v - __bfloat162float(h));
            Whi[m * W_PITCH + k] = h;
            Wlo[m * W_PITCH + k] = l;
        }
        if (tid < KK) bss[tid] = bspan[g * KK + tid];
    }
    __syncthreads();

    // ---- Phase A: tensor-core mini-GEMM ----
    {
        const int warp = tid >> 5, lane = tid & 31;
        const int mt = warp & 3;             // ks-row tile (16 rows)
        const int nh = warp >> 2;            // pixel half (64 px)

        // preload A fragments (W hi/lo), 4 k-steps
        uint32_t Ahi[4][4], Alo[4][4];
        {
            const uint32_t arow = (uint32_t)(mt * 16 + (lane & 15));
            const uint32_t acol = (uint32_t)((lane >> 4) * 8);
            const uint32_t aoff = (arow * W_PITCH + acol) * 2;
            const uint32_t ahb  = smb + W_HI_F * 4 + aoff;
            const uint32_t alb  = smb + W_LO_F * 4 + aoff;
            #pragma unroll
            for (int ks = 0; ks < 4; ++ks) {
                ldmatrix_x4(Ahi[ks][0], Ahi[ks][1], Ahi[ks][2], Ahi[ks][3], ahb + ks * 32);
                ldmatrix_x4(Alo[ks][0], Alo[ks][1], Alo[ks][2], Alo[ks][3], alb + ks * 32);
            }
        }

        float acc[8][4];
        #pragma unroll
        for (int i = 0; i < 8; ++i)
            #pragma unroll
            for (int j = 0; j < 4; ++j) acc[i][j] = 0.f;

        const uint32_t brow = (uint32_t)(lane & 15);
        #pragma unroll
        for (int nt = 0; nt < 8; ++nt) {
            const int n0 = nh * 64 + nt * 8;
            #pragma unroll
            for (int ks = 0; ks < 4; ++ks) {
                const uint32_t boff = ((ks * 16 + brow) * T_PITCH + (uint32_t)n0) * 2;
                uint32_t bh0, bh1, bl0, bl1;
                ldmatrix_x2_trans(bh0, bh1, smb + T_HI_F * 4 + boff);
                ldmatrix_x2_trans(bl0, bl1, smb + T_LO_F * 4 + boff);
                mma_bf16(acc[nt], Ahi[ks], bh0, bh1);   // hi*hi
                mma_bf16(acc[nt], Ahi[ks], bl0, bl1);   // hi*lo
                mma_bf16(acc[nt], Alo[ks], bh0, bh1);   // lo*hi
            }
        }

        // store C (+bias) to ks; rows >= 49 discarded
        const int r0 = mt * 16 + (lane >> 2);
        const int r1 = r0 + 8;
        const int cc = (lane & 3) * 2;
        #pragma unroll
        for (int nt = 0; nt < 8; ++nt) {
            const int n0 = nh * 64 + nt * 8 + cc;
            if (r0 < KK) {
                const float bias = bss[r0];
                float2 v; v.x = acc[nt][0] + bias; v.y = acc[nt][1] + bias;
                *reinterpret_cast<float2*>(ksp + r0 * 128 + n0) = v;
            }
            if (r1 < KK) {
                const float bias = bss[r1];
                float2 v; v.x = acc[nt][2] + bias; v.y = acc[nt][3] + bias;
                *reinterpret_cast<float2*>(ksp + r1 * 128 + n0) = v;
            }
        }
    }
    __syncthreads();   // ks complete; T/W reads done -> safe to overwrite with xs

    // ---- load x halo: 16 ch x 8 rows x 72 cols (rows y0-3..y0+4, cols -3..68) ----
    {
        const float* xg = x + ((size_t)b * CH + g * CPG) * NPIX;
        for (int i = tid; i < CPG * 8 * 72; i += 256) {
            const int c  = i / 576;
            const int r  = (i % 576) / 72;
            const int xi = i % 72;
            const int gy = y0 + r - 3;
            const int gx = xi - 3;
            float v = 0.f;
            if ((unsigned)gy < HH && (unsigned)gx < WW)
                v = xg[(size_t)c * NPIX + gy * WW + gx];
            xs[i] = v;
        }
    }
    __syncthreads();

    // ---- Phase B: apply. thread = (cg 0..7 -> 2 ch) x (px4 0..31 -> 4 px) ----
    {
        const int px4 = tid & 31;
        const int cg  = tid >> 5;
        const int yy  = px4 >> 4;
        const int xx  = (px4 & 15) * 4;
        const int c0  = cg * 2;

        float acc[2][4];
        #pragma unroll
        for (int i = 0; i < 2; ++i)
            #pragma unroll
            for (int j = 0; j < 4; ++j) acc[i][j] = 0.f;

        const float4* ks4 = reinterpret_cast<const float4*>(ksp);

        #pragma unroll
        for (int ti = 0; ti < 7; ++ti) {
            float w0[12], w1[12];
            const float* r0 = xs + (size_t)(c0 * 8 + yy + ti) * 72 + xx;
            const float* r1 = xs + (size_t)((c0 + 1) * 8 + yy + ti) * 72 + xx;
            *reinterpret_cast<float4*>(w0 + 0) = *reinterpret_cast<const float4*>(r0 + 0);
            *reinterpret_cast<float4*>(w0 + 4) = *reinterpret_cast<const float4*>(r0 + 4);
            *reinterpret_cast<float4*>(w0 + 8) = *reinterpret_cast<const float4*>(r0 + 8);
            *reinterpret_cast<float4*>(w1 + 0) = *reinterpret_cast<const float4*>(r1 + 0);
            *reinterpret_cast<float4*>(w1 + 4) = *reinterpret_cast<const float4*>(r1 + 4);
            *reinterpret_cast<float4*>(w1 + 8) = *reinterpret_cast<const float4*>(r1 + 8);
            #pragma unroll
            for (int tj = 0; tj < 7; ++tj) {
                const float4 kv = ks4[(ti * 7 + tj) * 32 + px4];
                acc[0][0] += kv.x * w0[tj + 0];
                acc[0][1] += kv.y * w0[tj + 1];
                acc[0][2] += kv.z * w0[tj + 2];
                acc[0][3] += kv.w * w0[tj + 3];
                acc[1][0] += kv.x * w1[tj + 0];
                acc[1][1] += kv.y * w1[tj + 1];
                acc[1][2] += kv.z * w1[tj + 2];
                acc[1][3] += kv.w * w1[tj + 3];
            }
        }

        #pragma unroll
        for (int ci = 0; ci < 2; ++ci) {
            const int c = g * CPG + c0 + ci;
            float4 v;
            v.x = acc[ci][0]; v.y = acc[ci][1]; v.z = acc[ci][2]; v.w = acc[ci][3];
            *reinterpret_cast<float4*>(out + ((size_t)b * CH + c) * NPIX + p0g + px4 * 4) = v;
        }
    }
}

// ============================================================================
extern "C" void kernel_launch(void* const* d_in, const int* in_sizes, int n_in,
                              void* d_out, int out_size) {
    const float* x   = (const float*)d_in[0];
    const float* wr  = (const float*)d_in[1];
    const float* br  = (const float*)d_in[2];
    const float* wsp = (const float*)d_in[3];
    const float* bsp = (const float*)d_in[4];
    float* out = (float*)d_out;

    cudaFuncSetAttribute(fused_kernel,
                         cudaFuncAttributeMaxDynamicSharedMemorySize, SMEM_BYTES);

    reduce_kernel<<<dim3(64, 2, BSZ), 256>>>(x, wr, br);
    fused_kernel<<<dim3(32, GRP, BSZ), 256, SMEM_BYTES>>>(x, wsp, bsp, out);
}

// round 8
// speedup vs baseline: 1.3691x; 1.3691x over previous
#include <cuda_runtime.h>
#include <cuda_bf16.h>
#include <cstdint>
#include <cstddef>

// ---- problem constants ----
#define CH    256
#define CR    64
#define GRP   16
#define CPG   16
#define KK    49
#define HH    64
#define WW    64
#define NPIX  4096
#define BSZ   4

// ---- device scratch ----
// t in bf16 hi/lo, tile-major: [b][tile(32)][k(64)][px(128)]  (2 MB each)
__device__ unsigned short g_thi[BSZ * 32 * CR * 128];
__device__ unsigned short g_tlo[BSZ * 32 * CR * 128];
// w_span pre-packed as m16n8k16 A-fragments: [g][mt(4)][ks(4)][hl(2)][lane(32)] uint4
__device__ uint4 g_wfrag[GRP * 4 * 4 * 2 * 32];        // 256 KB

// ============================================================================
// PTX helpers
// ============================================================================
__device__ __forceinline__ uint32_t smem_u32(const void* p) {
    uint32_t a;
    asm("{ .reg .u64 t; cvta.to.shared.u64 t, %1; cvt.u32.u64 %0, t; }"
        : "=r"(a) : "l"(p));
    return a;
}
__device__ __forceinline__ void ldmatrix_x4_trans(uint32_t& b0, uint32_t& b1,
                                                  uint32_t& b2, uint32_t& b3, uint32_t addr) {
    asm volatile("ldmatrix.sync.aligned.m8n8.x4.trans.shared.b16 {%0,%1,%2,%3}, [%4];"
                 : "=r"(b0), "=r"(b1), "=r"(b2), "=r"(b3) : "r"(addr));
}
__device__ __forceinline__ void mma_bf16(float* c, const uint32_t* a,
                                         uint32_t b0, uint32_t b1) {
    asm volatile("mma.sync.aligned.m16n8k16.row.col.f32.bf16.bf16.f32 "
                 "{%0,%1,%2,%3}, {%4,%5,%6,%7}, {%8,%9}, {%0,%1,%2,%3};"
                 : "+f"(c[0]), "+f"(c[1]), "+f"(c[2]), "+f"(c[3])
                 : "r"(a[0]), "r"(a[1]), "r"(a[2]), "r"(a[3]), "r"(b0), "r"(b1));
}

// ---- fused smem layout (float offsets). Region0: T hi/lo (phaseA) | xs (phaseB)
#define T_PITCH_B 272       // 136 bf16 per row; 272B = 17 x 16B -> conflict-free
#define T_LO_OFF  17408     // bytes
#define XS_F      0         // 9216 floats (36864 B) aliases T region (34816 B)
#define KS_F      9216      // 49*128 floats
#define BS_F      15488     // 56 floats
#define SMEM_FLOATS 15552
#define SMEM_BYTES  (SMEM_FLOATS * 4)

// ============================================================================
// Kernel 0: pack w_span into A-fragment scratch (runs once per launch, ~2 us)
// ============================================================================
__global__ void __launch_bounds__(256) wprep_kernel(const float* __restrict__ wspan) {
    const int idx  = blockIdx.x * 256 + threadIdx.x;   // 16384 total
    const int lane = idx & 31;
    const int hl   = (idx >> 5) & 1;
    const int ks   = (idx >> 6) & 3;
    const int mt   = (idx >> 8) & 3;
    const int g    = idx >> 10;

    uint32_t r[4];
    #pragma unroll
    for (int q = 0; q < 4; ++q) {
        const int m = mt * 16 + (lane >> 2) + (q & 1) * 8;
        const int k = ks * 16 + (lane & 3) * 2 + (q >> 1) * 8;
        const float v0 = (m < KK) ? wspan[(size_t)(g * KK + m) * 64 + k]     : 0.f;
        const float v1 = (m < KK) ? wspan[(size_t)(g * KK + m) * 64 + k + 1] : 0.f;
        const __nv_bfloat16 h0 = __float2bfloat16(v0);
        const __nv_bfloat16 h1 = __float2bfloat16(v1);
        if (hl == 0) {
            r[q] = ((uint32_t)__bfloat16_as_ushort(h1) << 16) | __bfloat16_as_ushort(h0);
        } else {
            const __nv_bfloat16 l0 = __float2bfloat16(v0 - __bfloat162float(h0));
            const __nv_bfloat16 l1 = __float2bfloat16(v1 - __bfloat162float(h1));
            r[q] = ((uint32_t)__bfloat16_as_ushort(l1) << 16) | __bfloat16_as_ushort(l0);
        }
    }
    g_wfrag[idx] = make_uint4(r[0], r[1], r[2], r[3]);
}

// ============================================================================
// Kernel 1: reduce -> writes t directly as bf16 hi/lo in tile-major layout
// ============================================================================
__global__ void __launch_bounds__(256) reduce_kernel(
        const float* __restrict__ x,
        const float* __restrict__ wr,
        const float* __restrict__ br) {
    __shared__ float4 ws4[32 * 64];
    const int b   = blockIdx.z;
    const int oc  = blockIdx.y;
    const int px0 = blockIdx.x * 64;
    const int tid = threadIdx.x;

    const float4* wsrc = reinterpret_cast<const float4*>(wr + (size_t)oc * 32 * CH);
    for (int i = tid; i < 2048; i += 256) ws4[i] = wsrc[i];
    __syncthreads();

    const int og = tid >> 5;
    const int pg = tid & 31;
    const int px = px0 + pg * 2;
    const float* xb = x + (size_t)b * CH * NPIX + px;

    float acc[4][2];
    #pragma unroll
    for (int i = 0; i < 4; ++i) { acc[i][0] = 0.f; acc[i][1] = 0.f; }

    #pragma unroll 4
    for (int k4 = 0; k4 < 64; ++k4) {
        const float2 x0 = *reinterpret_cast<const float2*>(xb + (size_t)(k4 * 4 + 0) * NPIX);
        const float2 x1 = *reinterpret_cast<const float2*>(xb + (size_t)(k4 * 4 + 1) * NPIX);
        const float2 x2 = *reinterpret_cast<const float2*>(xb + (size_t)(k4 * 4 + 2) * NPIX);
        const float2 x3 = *reinterpret_cast<const float2*>(xb + (size_t)(k4 * 4 + 3) * NPIX);
        #pragma unroll
        for (int oi = 0; oi < 4; ++oi) {
            const float4 wv = ws4[(og * 4 + oi) * 64 + k4];
            acc[oi][0] += wv.x * x0.x + wv.y * x1.x + wv.z * x2.x + wv.w * x3.x;
            acc[oi][1] += wv.x * x0.y + wv.y * x1.y + wv.z * x2.y + wv.w * x3.y;
        }
    }

    const int tile = px >> 7;
    const int pc   = px & 127;
    #pragma unroll
    for (int oi = 0; oi < 4; ++oi) {
        const int o = oc * 32 + og * 4 + oi;
        const float bias = br[o];
        const float vx = acc[oi][0] + bias;
        const float vy = acc[oi][1] + bias;
        const __nv_bfloat16 h0 = __float2bfloat16(vx);
        const __nv_bfloat16 h1 = __float2bfloat16(vy);
        const uint32_t hp = ((uint32_t)__bfloat16_as_ushort(h1) << 16) | __bfloat16_as_ushort(h0);
        const __nv_bfloat16 l0 = __float2bfloat16(vx - __bfloat162float(h0));
        const __nv_bfloat16 l1 = __float2bfloat16(vy - __bfloat162float(h1));
        const uint32_t lp = ((uint32_t)__bfloat16_as_ushort(l1) << 16) | __bfloat16_as_ushort(l0);
        const size_t base = (((size_t)b * 32 + tile) * CR + o) * 128 + pc;
        *reinterpret_cast<uint32_t*>(g_thi + base) = hp;
        *reinterpret_cast<uint32_t*>(g_tlo + base) = lp;
    }
}

// ============================================================================
// Kernel 2: fused span (mma.sync bf16 3-pass) + involution apply
// Block = (tile, g, b) = 2048; 256 threads; smem 62.2 KB -> 3 CTAs/SM.
// ============================================================================
extern __shared__ float sm[];

__global__ void __launch_bounds__(256, 3) fused_kernel(
        const float* __restrict__ x,
        const float* __restrict__ bspan,
        float* __restrict__ out) {
    const int tile = blockIdx.x;
    const int g    = blockIdx.y;
    const int b    = blockIdx.z;
    const int tid  = threadIdx.x;
    const int p0g  = tile * 128;
    const int y0   = tile * 2;

    const uint32_t smb = smem_u32(sm);
    float* xs  = sm + XS_F;
    float* ksp = sm + KS_F;
    float* bss = sm + BS_F;

    // ---- stage T hi/lo tiles (pure 16B copies, no conversion) + bias ----
    {
        const uint4* sh = reinterpret_cast<const uint4*>(
            g_thi + (size_t)(b * 32 + tile) * CR * 128);
        const uint4* sl = reinterpret_cast<const uint4*>(
            g_tlo + (size_t)(b * 32 + tile) * CR * 128);
        char* smc = reinterpret_cast<char*>(sm);
        #pragma unroll
        for (int i = tid; i < 1024; i += 256) {
            const int off = (i >> 4) * T_PITCH_B + (i & 15) * 16;
            *reinterpret_cast<uint4*>(smc + off)            = sh[i];
            *reinterpret_cast<uint4*>(smc + T_LO_OFF + off) = sl[i];
        }
        if (tid < KK) bss[tid] = bspan[g * KK + tid];
    }
    __syncthreads();

    // ---- Phase A: tensor-core mini-GEMM ks[49][128] = W @ t ----
    {
        const int warp = tid >> 5, lane = tid & 31;
        const int mt = warp & 3;             // ks-row tile (16 rows)
        const int nh = warp >> 2;            // pixel half (64 px)

        // W fragments: 8 coalesced LDG.128 from L2-hot pre-packed table
        uint4 Whi[4], Wlo[4];
        const uint4* wf = g_wfrag + (size_t)(g * 4 + mt) * 256 + lane;
        #pragma unroll
        for (int ks = 0; ks < 4; ++ks) {
            Whi[ks] = wf[ks * 64];
            Wlo[ks] = wf[ks * 64 + 32];
        }

        float acc[8][4];
        #pragma unroll
        for (int i = 0; i < 8; ++i)
            #pragma unroll
            for (int j = 0; j < 4; ++j) acc[i][j] = 0.f;

        const uint32_t thb = smb;
        const uint32_t tlb = smb + T_LO_OFF;
        #pragma unroll
        for (int ks = 0; ks < 4; ++ks) {
            const uint32_t* Ah = reinterpret_cast<const uint32_t*>(&Whi[ks]);
            const uint32_t* Al = reinterpret_cast<const uint32_t*>(&Wlo[ks]);
            #pragma unroll
            for (int np = 0; np < 4; ++np) {
                const uint32_t off =
                    (uint32_t)((ks * 16 + (lane & 15)) * T_PITCH_B +
                               (nh * 64 + np * 16 + (lane >> 4) * 8) * 2);
                uint32_t h0, h1, h2, h3, l0, l1, l2, l3;
                ldmatrix_x4_trans(h0, h1, h2, h3, thb + off);
                ldmatrix_x4_trans(l0, l1, l2, l3, tlb + off);
                mma_bf16(acc[np * 2 + 0], Ah, h0, h1);   // hi*hi
                mma_bf16(acc[np * 2 + 0], Ah, l0, l1);   // hi*lo
                mma_bf16(acc[np * 2 + 0], Al, h0, h1);   // lo*hi
                mma_bf16(acc[np * 2 + 1], Ah, h2, h3);
                mma_bf16(acc[np * 2 + 1], Ah, l2, l3);
                mma_bf16(acc[np * 2 + 1], Al, h2, h3);
            }
        }

        // store C (+bias) to ks; rows >= 49 discarded
        const int r0 = mt * 16 + (lane >> 2);
        const int r1 = r0 + 8;
        const int cc = (lane & 3) * 2;
        #pragma unroll
        for (int nt = 0; nt < 8; ++nt) {
            const int n0 = nh * 64 + nt * 8 + cc;
            if (r0 < KK) {
                const float bias = bss[r0];
                float2 v; v.x = acc[nt][0] + bias; v.y = acc[nt][1] + bias;
                *reinterpret_cast<float2*>(ksp + r0 * 128 + n0) = v;
            }
            if (r1 < KK) {
                const float bias = bss[r1];
                float2 v; v.x = acc[nt][2] + bias; v.y = acc[nt][3] + bias;
                *reinterpret_cast<float2*>(ksp + r1 * 128 + n0) = v;
            }
        }
    }
    __syncthreads();   // ks complete; T reads done -> xs may overwrite region0

    // ---- load x halo: 16 ch x 8 rows x 72 cols ----
    {
        const float* xg = x + ((size_t)b * CH + g * CPG) * NPIX;
        for (int i = tid; i < CPG * 8 * 72; i += 256) {
            const int c  = i / 576;
            const int r  = (i % 576) / 72;
            const int xi = i % 72;
            const int gy = y0 + r - 3;
            const int gx = xi - 3;
            float v = 0.f;
            if ((unsigned)gy < HH && (unsigned)gx < WW)
                v = xg[(size_t)c * NPIX + gy * WW + gx];
            xs[i] = v;
        }
    }
    __syncthreads();

    // ---- Phase B: apply. thread = (cg 0..7 -> 2 ch) x (px4 0..31 -> 4 px) ----
    {
        const int px4 = tid & 31;
        const int cg  = tid >> 5;
        const int yy  = px4 >> 4;
        const int xx  = (px4 & 15) * 4;
        const int c0  = cg * 2;

        float acc[2][4];
        #pragma unroll
        for (int i = 0; i < 2; ++i)
            #pragma unroll
            for (int j = 0; j < 4; ++j) acc[i][j] = 0.f;

        const float4* ks4 = reinterpret_cast<const float4*>(ksp);

        #pragma unroll
        for (int ti = 0; ti < 7; ++ti) {
            float w0[12], w1[12];
            const float* r0 = xs + (size_t)(c0 * 8 + yy + ti) * 72 + xx;
            const float* r1 = xs + (size_t)((c0 + 1) * 8 + yy + ti) * 72 + xx;
            *reinterpret_cast<float4*>(w0 + 0) = *reinterpret_cast<const float4*>(r0 + 0);
            *reinterpret_cast<float4*>(w0 + 4) = *reinterpret_cast<const float4*>(r0 + 4);
            *reinterpret_cast<float4*>(w0 + 8) = *reinterpret_cast<const float4*>(r0 + 8);
            *reinterpret_cast<float4*>(w1 + 0) = *reinterpret_cast<const float4*>(r1 + 0);
            *reinterpret_cast<float4*>(w1 + 4) = *reinterpret_cast<const float4*>(r1 + 4);
            *reinterpret_cast<float4*>(w1 + 8) = *reinterpret_cast<const float4*>(r1 + 8);
            #pragma unroll
            for (int tj = 0; tj < 7; ++tj) {
                const float4 kv = ks4[(ti * 7 + tj) * 32 + px4];
                acc[0][0] += kv.x * w0[tj + 0];
                acc[0][1] += kv.y * w0[tj + 1];
                acc[0][2] += kv.z * w0[tj + 2];
                acc[0][3] += kv.w * w0[tj + 3];
                acc[1][0] += kv.x * w1[tj + 0];
                acc[1][1] += kv.y * w1[tj + 1];
                acc[1][2] += kv.z * w1[tj + 2];
                acc[1][3] += kv.w * w1[tj + 3];
            }
        }

        #pragma unroll
        for (int ci = 0; ci < 2; ++ci) {
            const int c = g * CPG + c0 + ci;
            float4 v;
            v.x = acc[ci][0]; v.y = acc[ci][1]; v.z = acc[ci][2]; v.w = acc[ci][3];
            *reinterpret_cast<float4*>(out + ((size_t)b * CH + c) * NPIX + p0g + px4 * 4) = v;
        }
    }
}

// ============================================================================
extern "C" void kernel_launch(void* const* d_in, const int* in_sizes, int n_in,
                              void* d_out, int out_size) {
    const float* x   = (const float*)d_in[0];
    const float* wr  = (const float*)d_in[1];
    const float* br  = (const float*)d_in[2];
    const float* wsp = (const float*)d_in[3];
    const float* bsp = (const float*)d_in[4];
    float* out = (float*)d_out;

    cudaFuncSetAttribute(fused_kernel,
                         cudaFuncAttributeMaxDynamicSharedMemorySize, SMEM_BYTES);

    wprep_kernel<<<64, 256>>>(wsp);
    reduce_kernel<<<dim3(64, 2, BSZ), 256>>>(x, wr, br);
    fused_kernel<<<dim3(32, GRP, BSZ), 256, SMEM_BYTES>>>(x, bsp, out);
}

// round 9
// speedup vs baseline: 1.5261x; 1.1147x over previous
#include <cuda_runtime.h>
#include <cuda_bf16.h>
#include <cstdint>
#include <cstddef>

// ---- problem constants ----
#define CH    256
#define CR    64
#define GRP   16
#define CPG   16
#define KK    49
#define HH    64
#define WW    64
#define NPIX  4096
#define BSZ   4

// ---- device scratch ----
// t in bf16 hi/lo, tile-major: [b][tile(32)][k(64)][px(128)]  (2 MB each)
__device__ unsigned short g_thi[BSZ * 32 * CR * 128];
__device__ unsigned short g_tlo[BSZ * 32 * CR * 128];
// w_span pre-packed as m16n8k16 A-fragments: [g][mt(4)][ks(4)][hl(2)][lane(32)] uint4
__device__ uint4 g_wfrag[GRP * 4 * 4 * 2 * 32];        // 256 KB

// ============================================================================
// PTX helpers
// ============================================================================
__device__ __forceinline__ uint32_t smem_u32(const void* p) {
    uint32_t a;
    asm("{ .reg .u64 t; cvta.to.shared.u64 t, %1; cvt.u32.u64 %0, t; }"
        : "=r"(a) : "l"(p));
    return a;
}
__device__ __forceinline__ void ldmatrix_x4_trans(uint32_t& b0, uint32_t& b1,
                                                  uint32_t& b2, uint32_t& b3, uint32_t addr) {
    asm volatile("ldmatrix.sync.aligned.m8n8.x4.trans.shared.b16 {%0,%1,%2,%3}, [%4];"
                 : "=r"(b0), "=r"(b1), "=r"(b2), "=r"(b3) : "r"(addr));
}
__device__ __forceinline__ void mma_bf16(float* c, const uint32_t* a,
                                         uint32_t b0, uint32_t b1) {
    asm volatile("mma.sync.aligned.m16n8k16.row.col.f32.bf16.bf16.f32 "
                 "{%0,%1,%2,%3}, {%4,%5,%6,%7}, {%8,%9}, {%0,%1,%2,%3};"
                 : "+f"(c[0]), "+f"(c[1]), "+f"(c[2]), "+f"(c[3])
                 : "r"(a[0]), "r"(a[1]), "r"(a[2]), "r"(a[3]), "r"(b0), "r"(b1));
}

// ---- fused smem layout (float offsets). Region0: T hi/lo (phaseA) | xs (phaseB)
#define T_PITCH_B 272       // 136 bf16 per row; 272B = 17 x 16B -> conflict-free
#define T_LO_OFF  17408     // bytes
#define XS_F      0         // 9216 floats (36864 B) aliases T region (34816 B)
#define KS_F      9216      // 49*128 floats
#define BS_F      15488     // 56 floats
#define SMEM_FLOATS 15552
#define SMEM_BYTES  (SMEM_FLOATS * 4)

// ============================================================================
// Kernel 1: reduce (+ merged w_span fragment packing on the y==2 slice)
// grid (64, 3, BSZ): y<2 -> reduce; y==2 && z==0 -> wprep; else no-op.
// ============================================================================
__global__ void __launch_bounds__(256) reduce_kernel(
        const float* __restrict__ x,
        const float* __restrict__ wr,
        const float* __restrict__ br,
        const float* __restrict__ wspan) {
    __shared__ float4 ws4[32 * 64];

    if (blockIdx.y == 2) {
        // ---- wprep slice: pack w_span into MMA A-fragment layout ----
        if (blockIdx.z != 0) return;
        const int idx  = blockIdx.x * 256 + threadIdx.x;   // 16384 total
        const int lane = idx & 31;
        const int hl   = (idx >> 5) & 1;
        const int ks   = (idx >> 6) & 3;
        const int mt   = (idx >> 8) & 3;
        const int g    = idx >> 10;

        uint32_t r[4];
        #pragma unroll
        for (int q = 0; q < 4; ++q) {
            const int m = mt * 16 + (lane >> 2) + (q & 1) * 8;
            const int k = ks * 16 + (lane & 3) * 2 + (q >> 1) * 8;
            const float v0 = (m < KK) ? wspan[(size_t)(g * KK + m) * 64 + k]     : 0.f;
            const float v1 = (m < KK) ? wspan[(size_t)(g * KK + m) * 64 + k + 1] : 0.f;
            const __nv_bfloat16 h0 = __float2bfloat16(v0);
            const __nv_bfloat16 h1 = __float2bfloat16(v1);
            if (hl == 0) {
                r[q] = ((uint32_t)__bfloat16_as_ushort(h1) << 16) | __bfloat16_as_ushort(h0);
            } else {
                const __nv_bfloat16 l0 = __float2bfloat16(v0 - __bfloat162float(h0));
                const __nv_bfloat16 l1 = __float2bfloat16(v1 - __bfloat162float(h1));
                r[q] = ((uint32_t)__bfloat16_as_ushort(l1) << 16) | __bfloat16_as_ushort(l0);
            }
        }
        g_wfrag[idx] = make_uint4(r[0], r[1], r[2], r[3]);
        return;
    }

    const int b   = blockIdx.z;
    const int oc  = blockIdx.y;
    const int px0 = blockIdx.x * 64;
    const int tid = threadIdx.x;

    const float4* wsrc = reinterpret_cast<const float4*>(wr + (size_t)oc * 32 * CH);
    for (int i = tid; i < 2048; i += 256) ws4[i] = wsrc[i];
    __syncthreads();

    const int og = tid >> 5;
    const int pg = tid & 31;
    const int px = px0 + pg * 2;
    const float* xb = x + (size_t)b * CH * NPIX + px;

    float acc[4][2];
    #pragma unroll
    for (int i = 0; i < 4; ++i) { acc[i][0] = 0.f; acc[i][1] = 0.f; }

    #pragma unroll 4
    for (int k4 = 0; k4 < 64; ++k4) {
        const float2 x0 = *reinterpret_cast<const float2*>(xb + (size_t)(k4 * 4 + 0) * NPIX);
        const float2 x1 = *reinterpret_cast<const float2*>(xb + (size_t)(k4 * 4 + 1) * NPIX);
        const float2 x2 = *reinterpret_cast<const float2*>(xb + (size_t)(k4 * 4 + 2) * NPIX);
        const float2 x3 = *reinterpret_cast<const float2*>(xb + (size_t)(k4 * 4 + 3) * NPIX);
        #pragma unroll
        for (int oi = 0; oi < 4; ++oi) {
            const float4 wv = ws4[(og * 4 + oi) * 64 + k4];
            acc[oi][0] += wv.x * x0.x + wv.y * x1.x + wv.z * x2.x + wv.w * x3.x;
            acc[oi][1] += wv.x * x0.y + wv.y * x1.y + wv.z * x2.y + wv.w * x3.y;
        }
    }

    const int tile = px >> 7;
    const int pc   = px & 127;
    #pragma unroll
    for (int oi = 0; oi < 4; ++oi) {
        const int o = oc * 32 + og * 4 + oi;
        const float bias = br[o];
        const float vx = acc[oi][0] + bias;
        const float vy = acc[oi][1] + bias;
        const __nv_bfloat16 h0 = __float2bfloat16(vx);
        const __nv_bfloat16 h1 = __float2bfloat16(vy);
        const uint32_t hp = ((uint32_t)__bfloat16_as_ushort(h1) << 16) | __bfloat16_as_ushort(h0);
        const __nv_bfloat16 l0 = __float2bfloat16(vx - __bfloat162float(h0));
        const __nv_bfloat16 l1 = __float2bfloat16(vy - __bfloat162float(h1));
        const uint32_t lp = ((uint32_t)__bfloat16_as_ushort(l1) << 16) | __bfloat16_as_ushort(l0);
        const size_t base = (((size_t)b * 32 + tile) * CR + o) * 128 + pc;
        *reinterpret_cast<uint32_t*>(g_thi + base) = hp;
        *reinterpret_cast<uint32_t*>(g_tlo + base) = lp;
    }
}

// ============================================================================
// Kernel 2: fused span (mma.sync bf16 3-pass) + involution apply
// Block = (tile, g, b) = 2048; 256 threads; smem 62.2 KB -> 3 CTAs/SM.
// ============================================================================
extern __shared__ float sm[];

__global__ void __launch_bounds__(256, 3) fused_kernel(
        const float* __restrict__ x,
        const float* __restrict__ bspan,
        float* __restrict__ out) {
    const int tile = blockIdx.x;
    const int g    = blockIdx.y;
    const int b    = blockIdx.z;
    const int tid  = threadIdx.x;
    const int p0g  = tile * 128;
    const int y0   = tile * 2;

    const uint32_t smb = smem_u32(sm);
    float* xs  = sm + XS_F;
    float* ksp = sm + KS_F;
    float* bss = sm + BS_F;

    // ---- stage T hi/lo tiles (pure 16B copies, no conversion) + bias ----
    {
        const uint4* sh = reinterpret_cast<const uint4*>(
            g_thi + (size_t)(b * 32 + tile) * CR * 128);
        const uint4* sl = reinterpret_cast<const uint4*>(
            g_tlo + (size_t)(b * 32 + tile) * CR * 128);
        char* smc = reinterpret_cast<char*>(sm);
        #pragma unroll
        for (int i = tid; i < 1024; i += 256) {
            const int off = (i >> 4) * T_PITCH_B + (i & 15) * 16;
            *reinterpret_cast<uint4*>(smc + off)            = sh[i];
            *reinterpret_cast<uint4*>(smc + T_LO_OFF + off) = sl[i];
        }
        if (tid < KK) bss[tid] = bspan[g * KK + tid];
    }
    __syncthreads();

    // ---- Phase A: tensor-core mini-GEMM ks[49][128] = W @ t ----
    {
        const int warp = tid >> 5, lane = tid & 31;
        const int mt = warp & 3;             // ks-row tile (16 rows)
        const int nh = warp >> 2;            // pixel half (64 px)

        // W fragments: 8 coalesced LDG.128 from L2-hot pre-packed table
        uint4 Whi[4], Wlo[4];
        const uint4* wf = g_wfrag + (size_t)(g * 4 + mt) * 256 + lane;
        #pragma unroll
        for (int ks = 0; ks < 4; ++ks) {
            Whi[ks] = wf[ks * 64];
            Wlo[ks] = wf[ks * 64 + 32];
        }

        float acc[8][4];
        #pragma unroll
        for (int i = 0; i < 8; ++i)
            #pragma unroll
            for (int j = 0; j < 4; ++j) acc[i][j] = 0.f;

        const uint32_t thb = smb;
        const uint32_t tlb = smb + T_LO_OFF;
        #pragma unroll
        for (int ks = 0; ks < 4; ++ks) {
            const uint32_t* Ah = reinterpret_cast<const uint32_t*>(&Whi[ks]);
            const uint32_t* Al = reinterpret_cast<const uint32_t*>(&Wlo[ks]);
            #pragma unroll
            for (int np = 0; np < 4; ++np) {
                const uint32_t off =
                    (uint32_t)((ks * 16 + (lane & 15)) * T_PITCH_B +
                               (nh * 64 + np * 16 + (lane >> 4) * 8) * 2);
                uint32_t h0, h1, h2, h3, l0, l1, l2, l3;
                ldmatrix_x4_trans(h0, h1, h2, h3, thb + off);
                ldmatrix_x4_trans(l0, l1, l2, l3, tlb + off);
                mma_bf16(acc[np * 2 + 0], Ah, h0, h1);   // hi*hi
                mma_bf16(acc[np * 2 + 0], Ah, l0, l1);   // hi*lo
                mma_bf16(acc[np * 2 + 0], Al, h0, h1);   // lo*hi
                mma_bf16(acc[np * 2 + 1], Ah, h2, h3);
                mma_bf16(acc[np * 2 + 1], Ah, l2, l3);
                mma_bf16(acc[np * 2 + 1], Al, h2, h3);
            }
        }

        // store C (+bias) to ks; rows >= 49 discarded
        const int r0 = mt * 16 + (lane >> 2);
        const int r1 = r0 + 8;
        const int cc = (lane & 3) * 2;
        #pragma unroll
        for (int nt = 0; nt < 8; ++nt) {
            const int n0 = nh * 64 + nt * 8 + cc;
            if (r0 < KK) {
                const float bias = bss[r0];
                float2 v; v.x = acc[nt][0] + bias; v.y = acc[nt][1] + bias;
                *reinterpret_cast<float2*>(ksp + r0 * 128 + n0) = v;
            }
            if (r1 < KK) {
                const float bias = bss[r1];
                float2 v; v.x = acc[nt][2] + bias; v.y = acc[nt][3] + bias;
                *reinterpret_cast<float2*>(ksp + r1 * 128 + n0) = v;
            }
        }
    }
    __syncthreads();   // ks complete; T reads done -> xs may overwrite region0

    // ---- load x halo: 16 ch x 8 rows x 72 cols ----
    {
        const float* xg = x + ((size_t)b * CH + g * CPG) * NPIX;
        for (int i = tid; i < CPG * 8 * 72; i += 256) {
            const int c  = i / 576;
            const int r  = (i % 576) / 72;
            const int xi = i % 72;
            const int gy = y0 + r - 3;
            const int gx = xi - 3;
            float v = 0.f;
            if ((unsigned)gy < HH && (unsigned)gx < WW)
                v = xg[(size_t)c * NPIX + gy * WW + gx];
            xs[i] = v;
        }
    }
    __syncthreads();

    // ---- Phase B: apply. 128 active threads = (cq 0..3 -> 4 ch) x (pg 0..31 -> 4 px)
    //      kv[7] held in regs across both channel-pair halves per ti:
    //      per thread 49 kv-LDS.128 + 84 window-LDS.128 for 784 FMA.
    if (tid < 128) {
        const int pg = tid & 31;
        const int cq = tid >> 5;
        const int yy = pg >> 4;
        const int xx = (pg & 15) * 4;
        const int c0 = cq * 4;

        float acc[4][4];
        #pragma unroll
        for (int i = 0; i < 4; ++i)
            #pragma unroll
            for (int j = 0; j < 4; ++j) acc[i][j] = 0.f;

        const float4* ks4 = reinterpret_cast<const float4*>(ksp);

        #pragma unroll
        for (int ti = 0; ti < 7; ++ti) {
            // kernel values for this ti row (7 taps x 4 px)
            float kv[7][4];
            #pragma unroll
            for (int tj = 0; tj < 7; ++tj)
                *reinterpret_cast<float4*>(kv[tj]) = ks4[(ti * 7 + tj) * 32 + pg];

            #pragma unroll
            for (int half = 0; half < 2; ++half) {
                float w0[12], w1[12];
                const float* r0 = xs + (size_t)((c0 + half * 2 + 0) * 8 + yy + ti) * 72 + xx;
                const float* r1 = xs + (size_t)((c0 + half * 2 + 1) * 8 + yy + ti) * 72 + xx;
                *reinterpret_cast<float4*>(w0 + 0) = *reinterpret_cast<const float4*>(r0 + 0);
                *reinterpret_cast<float4*>(w0 + 4) = *reinterpret_cast<const float4*>(r0 + 4);
                *reinterpret_cast<float4*>(w0 + 8) = *reinterpret_cast<const float4*>(r0 + 8);
                *reinterpret_cast<float4*>(w1 + 0) = *reinterpret_cast<const float4*>(r1 + 0);
                *reinterpret_cast<float4*>(w1 + 4) = *reinterpret_cast<const float4*>(r1 + 4);
                *reinterpret_cast<float4*>(w1 + 8) = *reinterpret_cast<const float4*>(r1 + 8);
                float* a0 = acc[half * 2 + 0];
                float* a1 = acc[half * 2 + 1];
                #pragma unroll
                for (int tj = 0; tj < 7; ++tj) {
                    a0[0] += kv[tj][0] * w0[tj + 0];
                    a0[1] += kv[tj][1] * w0[tj + 1];
                    a0[2] += kv[tj][2] * w0[tj + 2];
                    a0[3] += kv[tj][3] * w0[tj + 3];
                    a1[0] += kv[tj][0] * w1[tj + 0];
                    a1[1] += kv[tj][1] * w1[tj + 1];
                    a1[2] += kv[tj][2] * w1[tj + 2];
                    a1[3] += kv[tj][3] * w1[tj + 3];
                }
            }
        }

        #pragma unroll
        for (int ci = 0; ci < 4; ++ci) {
            const int c = g * CPG + c0 + ci;
            float4 v;
            v.x = acc[ci][0]; v.y = acc[ci][1]; v.z = acc[ci][2]; v.w = acc[ci][3];
            *reinterpret_cast<float4*>(out + ((size_t)b * CH + c) * NPIX + p0g + pg * 4) = v;
        }
    }
}

// ============================================================================
extern "C" void kernel_launch(void* const* d_in, const int* in_sizes, int n_in,
                              void* d_out, int out_size) {
    const float* x   = (const float*)d_in[0];
    const float* wr  = (const float*)d_in[1];
    const float* br  = (const float*)d_in[2];
    const float* wsp = (const float*)d_in[3];
    const float* bsp = (const float*)d_in[4];
    float* out = (float*)d_out;

    cudaFuncSetAttribute(fused_kernel,
                         cudaFuncAttributeMaxDynamicSharedMemorySize, SMEM_BYTES);

    reduce_kernel<<<dim3(64, 3, BSZ), 256>>>(x, wr, br, wsp);
    fused_kernel<<<dim3(32, GRP, BSZ), 256, SMEM_BYTES>>>(x, bsp, out);
}